// round 1
// baseline (speedup 1.0000x reference)
#include <cuda_runtime.h>
#include <cstdint>

// Problem constants
#define BB 4
#define CC_TOT 256
#define HH 128
#define WW 416
#define DD 81
#define MAXD 40

// Tiling
#define W_TILE 104          // 4 tiles * 104 = 416 exactly
#define RW (W_TILE + 2*MAXD) // 184
#define CCHUNK 16           // channels per smem chunk
#define NCHUNK (CC_TOT / CCHUNK) // 16
#define THREADS 128
#define L_F4 (W_TILE/4)     // 26
#define R_F4 (RW/4)         // 46
#define LD_PER_CHUNK (CCHUNK * (L_F4 + R_F4)) // 16*72 = 1152 -> 9 per thread

__device__ __forceinline__ void cp16(void* smem, const void* gmem) {
    uint32_t s = (uint32_t)__cvta_generic_to_shared(smem);
    asm volatile("cp.async.cg.shared.global [%0], [%1], 16;\n" :: "r"(s), "l"(gmem));
}

__global__ __launch_bounds__(THREADS, 4)
void corr_kernel(const float* __restrict__ left,
                 const float* __restrict__ right,
                 float* __restrict__ out) {
    __shared__ float Ls[2][CCHUNK][W_TILE];
    __shared__ float Rs[2][CCHUNK][RW];

    const int tile = blockIdx.x;   // 0..3
    const int h    = blockIdx.y;   // 0..127
    const int b    = blockIdx.z;   // 0..3
    const int w0   = tile * W_TILE;

    const int tid = threadIdx.x;
    const int row = tid % 9;       // d-row: d in [9*row, 9*row+8]
    const int col = tid / 9;       // w-col: w in [8*col, 8*col+7]
    const bool active = (col < 13);

    const size_t plane = (size_t)HH * WW;                 // per-channel plane
    const float* lbase = left  + ((size_t)b * CC_TOT * HH + h) * WW;
    const float* rbase = right + ((size_t)b * CC_TOT * HH + h) * WW;

    // ---- async chunk loader: CCHUNK rows of (26 L float4 + 46 R float4) ----
    auto load_chunk = [&](int ch, int buf) {
        const int c0 = ch * CCHUNK;
        #pragma unroll
        for (int it = 0; it < LD_PER_CHUNK / THREADS; it++) {
            int i   = tid + it * THREADS;
            int cc  = i / (L_F4 + R_F4);
            int pos = i % (L_F4 + R_F4);
            int c   = c0 + cc;
            if (pos < L_F4) {
                const float* g = lbase + (size_t)c * plane + w0 + pos * 4;
                cp16(&Ls[buf][cc][pos * 4], g);
            } else {
                int p  = pos - L_F4;
                int wg = w0 - MAXD + p * 4;    // global w of this float4 (4-aligned, all-in or all-out)
                float4* dst = (float4*)&Rs[buf][cc][p * 4];
                if (wg >= 0 && wg + 3 < WW) {
                    cp16(dst, rbase + (size_t)c * plane + wg);
                } else {
                    *dst = make_float4(0.f, 0.f, 0.f, 0.f);
                }
            }
        }
    };

    // prologue
    load_chunk(0, 0);
    asm volatile("cp.async.commit_group;\n" ::: "memory");

    float acc[9][8];
    #pragma unroll
    for (int j = 0; j < 9; j++)
        #pragma unroll
        for (int k = 0; k < 8; k++) acc[j][k] = 0.f;

    const int lw  = col * 8;
    const int rwi = col * 8 + row * 9;   // Rs local index of first needed R

    for (int ch = 0; ch < NCHUNK; ch++) {
        const int buf = ch & 1;
        if (ch + 1 < NCHUNK) {
            load_chunk(ch + 1, buf ^ 1);
            asm volatile("cp.async.commit_group;\n" ::: "memory");
            asm volatile("cp.async.wait_group 1;\n" ::: "memory");
        } else {
            asm volatile("cp.async.wait_group 0;\n" ::: "memory");
        }
        __syncthreads();

        if (active) {
            #pragma unroll 2
            for (int c = 0; c < CCHUNK; c++) {
                float l[8], r[16];
                #pragma unroll
                for (int k = 0; k < 8; k++)  l[k] = Ls[buf][c][lw + k];
                #pragma unroll
                for (int k = 0; k < 16; k++) r[k] = Rs[buf][c][rwi + k];
                #pragma unroll
                for (int j = 0; j < 9; j++)
                    #pragma unroll
                    for (int k = 0; k < 8; k++)
                        acc[j][k] = fmaf(l[k], r[j + k], acc[j][k]);
            }
        }
        __syncthreads();
    }

    // ---- epilogue: scale by 1/C, vectorized stores ----
    if (active) {
        const float scale = 1.0f / (float)CC_TOT;
        const int wbase = w0 + col * 8;
        #pragma unroll
        for (int j = 0; j < 9; j++) {
            int d = row * 9 + j;
            float* o = out + (((size_t)b * DD + d) * HH + h) * WW + wbase;
            float4 v0, v1;
            v0.x = acc[j][0] * scale; v0.y = acc[j][1] * scale;
            v0.z = acc[j][2] * scale; v0.w = acc[j][3] * scale;
            v1.x = acc[j][4] * scale; v1.y = acc[j][5] * scale;
            v1.z = acc[j][6] * scale; v1.w = acc[j][7] * scale;
            ((float4*)o)[0] = v0;
            ((float4*)o)[1] = v1;
        }
    }
}

extern "C" void kernel_launch(void* const* d_in, const int* in_sizes, int n_in,
                              void* d_out, int out_size) {
    const float* left  = (const float*)d_in[0];
    const float* right = (const float*)d_in[1];
    float* out = (float*)d_out;
    (void)in_sizes; (void)n_in; (void)out_size;

    dim3 grid(WW / W_TILE, HH, BB);   // (4, 128, 4)
    dim3 block(THREADS);
    corr_kernel<<<grid, block>>>(left, right, out);
}

// round 2
// speedup vs baseline: 1.0002x; 1.0002x over previous
#include <cuda_runtime.h>
#include <cstdint>

// Problem constants
#define BB 4
#define CC_TOT 256
#define HH 128
#define WW 416
#define DD 81
#define MAXD 40

// Tiling
#define W_TILE 104          // 4 tiles * 104 = 416 exactly
#define RW (W_TILE + 2*MAXD) // 184
#define CCHUNK 16           // channels per smem chunk
#define NCHUNK (CC_TOT / CCHUNK) // 16
#define THREADS 128
#define L_F4 (W_TILE/4)     // 26
#define R_F4 (RW/4)         // 46
#define LD_PER_CHUNK (CCHUNK * (L_F4 + R_F4)) // 16*72 = 1152 -> 9 per thread

__device__ __forceinline__ void cp16(void* smem, const void* gmem) {
    uint32_t s = (uint32_t)__cvta_generic_to_shared(smem);
    asm volatile("cp.async.cg.shared.global [%0], [%1], 16;\n" :: "r"(s), "l"(gmem));
}

__global__ __launch_bounds__(THREADS, 4)
void corr_kernel(const float* __restrict__ left,
                 const float* __restrict__ right,
                 float* __restrict__ out) {
    __shared__ float Ls[2][CCHUNK][W_TILE];
    __shared__ float Rs[2][CCHUNK][RW];

    const int tile = blockIdx.x;   // 0..3
    const int h    = blockIdx.y;   // 0..127
    const int b    = blockIdx.z;   // 0..3
    const int w0   = tile * W_TILE;

    const int tid = threadIdx.x;
    const int row = tid % 9;       // d-row: d in [9*row, 9*row+8]
    const int col = tid / 9;       // w-col: w in [8*col, 8*col+7]
    const bool active = (col < 13);

    const size_t plane = (size_t)HH * WW;                 // per-channel plane
    const float* lbase = left  + ((size_t)b * CC_TOT * HH + h) * WW;
    const float* rbase = right + ((size_t)b * CC_TOT * HH + h) * WW;

    // ---- async chunk loader: CCHUNK rows of (26 L float4 + 46 R float4) ----
    auto load_chunk = [&](int ch, int buf) {
        const int c0 = ch * CCHUNK;
        #pragma unroll
        for (int it = 0; it < LD_PER_CHUNK / THREADS; it++) {
            int i   = tid + it * THREADS;
            int cc  = i / (L_F4 + R_F4);
            int pos = i % (L_F4 + R_F4);
            int c   = c0 + cc;
            if (pos < L_F4) {
                const float* g = lbase + (size_t)c * plane + w0 + pos * 4;
                cp16(&Ls[buf][cc][pos * 4], g);
            } else {
                int p  = pos - L_F4;
                int wg = w0 - MAXD + p * 4;    // global w of this float4 (4-aligned, all-in or all-out)
                float4* dst = (float4*)&Rs[buf][cc][p * 4];
                if (wg >= 0 && wg + 3 < WW) {
                    cp16(dst, rbase + (size_t)c * plane + wg);
                } else {
                    *dst = make_float4(0.f, 0.f, 0.f, 0.f);
                }
            }
        }
    };

    // prologue
    load_chunk(0, 0);
    asm volatile("cp.async.commit_group;\n" ::: "memory");

    float acc[9][8];
    #pragma unroll
    for (int j = 0; j < 9; j++)
        #pragma unroll
        for (int k = 0; k < 8; k++) acc[j][k] = 0.f;

    const int lw  = col * 8;
    const int rwi = col * 8 + row * 9;   // Rs local index of first needed R

    for (int ch = 0; ch < NCHUNK; ch++) {
        const int buf = ch & 1;
        if (ch + 1 < NCHUNK) {
            load_chunk(ch + 1, buf ^ 1);
            asm volatile("cp.async.commit_group;\n" ::: "memory");
            asm volatile("cp.async.wait_group 1;\n" ::: "memory");
        } else {
            asm volatile("cp.async.wait_group 0;\n" ::: "memory");
        }
        __syncthreads();

        if (active) {
            #pragma unroll 2
            for (int c = 0; c < CCHUNK; c++) {
                float l[8], r[16];
                #pragma unroll
                for (int k = 0; k < 8; k++)  l[k] = Ls[buf][c][lw + k];
                #pragma unroll
                for (int k = 0; k < 16; k++) r[k] = Rs[buf][c][rwi + k];
                #pragma unroll
                for (int j = 0; j < 9; j++)
                    #pragma unroll
                    for (int k = 0; k < 8; k++)
                        acc[j][k] = fmaf(l[k], r[j + k], acc[j][k]);
            }
        }
        __syncthreads();
    }

    // ---- epilogue: scale by 1/C, vectorized stores ----
    if (active) {
        const float scale = 1.0f / (float)CC_TOT;
        const int wbase = w0 + col * 8;
        #pragma unroll
        for (int j = 0; j < 9; j++) {
            int d = row * 9 + j;
            float* o = out + (((size_t)b * DD + d) * HH + h) * WW + wbase;
            float4 v0, v1;
            v0.x = acc[j][0] * scale; v0.y = acc[j][1] * scale;
            v0.z = acc[j][2] * scale; v0.w = acc[j][3] * scale;
            v1.x = acc[j][4] * scale; v1.y = acc[j][5] * scale;
            v1.z = acc[j][6] * scale; v1.w = acc[j][7] * scale;
            ((float4*)o)[0] = v0;
            ((float4*)o)[1] = v1;
        }
    }
}

extern "C" void kernel_launch(void* const* d_in, const int* in_sizes, int n_in,
                              void* d_out, int out_size) {
    const float* left  = (const float*)d_in[0];
    const float* right = (const float*)d_in[1];
    float* out = (float*)d_out;
    (void)in_sizes; (void)n_in; (void)out_size;

    dim3 grid(WW / W_TILE, HH, BB);   // (4, 128, 4)
    dim3 block(THREADS);
    corr_kernel<<<grid, block>>>(left, right, out);
}

// round 6
// speedup vs baseline: 1.1438x; 1.1436x over previous
#include <cuda_runtime.h>
#include <cuda_fp16.h>
#include <mma.h>
#include <cstdint>

using namespace nvcuda;

#define BB    4
#define CCH   256
#define HH    128
#define WWI   416
#define DDI   81
#define PLANE (HH*WWI)
#define MAXD  40

#define NT    208            // N tile
#define NTH   256
#define MSTEP 96             // m0 in {0,96,192,288}; 288+128=416, no OOB

#define A_LD  136            // [k][m] halves, padded (272B rows)
#define B_LD  216            // [k][n] halves, padded (432B rows)
#define A_BYTES (CCH * A_LD * 2)       // 69632
#define B_BYTES (CCH * B_LD * 2)       // 110592
#define SMEM_BYTES (A_BYTES + B_BYTES) // 180224

__global__ __launch_bounds__(NTH, 1)
void corr_wmma(const float* __restrict__ left,
               const float* __restrict__ right,
               float* __restrict__ out) {
    extern __shared__ __align__(16) char smem[];
    __half* As = (__half*)smem;                   // [256][136]
    __half* Bs = (__half*)(smem + A_BYTES);       // [256][216]
    float*  Ds = (float*)smem;                    // reused: [128][208]

    const int tid = threadIdx.x;
    const int wid = tid >> 5;
    const int m0  = blockIdx.x * MSTEP;
    const int h   = blockIdx.y, b = blockIdx.z;
    const float* lbase = left  + ((size_t)b * CCH * HH + h) * WWI;
    const float* rbase = right + ((size_t)b * CCH * HH + h) * WWI;
    const float S = 1.0f / 256.0f;   // exact power of two, folded into A

    // ---------- fill A: L[c, m0+m] * S -> half, As[k][m] ----------
    {
        const int mi = (tid & 31) * 4;    // 0..124
        const int kr = tid >> 5;          // 0..7
        #pragma unroll 4
        for (int k0 = 0; k0 < CCH; k0 += 8) {
            const int k = k0 + kr;
            float4 v = *(const float4*)(lbase + (size_t)k * PLANE + m0 + mi);
            __half2 h0 = __floats2half2_rn(v.x * S, v.y * S);
            __half2 h1 = __floats2half2_rn(v.z * S, v.w * S);
            uint2 pk = make_uint2(*(uint32_t*)&h0, *(uint32_t*)&h1);
            *(uint2*)(As + k * A_LD + mi) = pk;    // 8B aligned: (k*136+mi)%4==0
        }
    }

    // ---------- fill B: R[c, m0-40+n] -> half, Bs[k][n], OOB=0 ----------
    if (tid < 208) {
        const int r = tid / 52;          // 0..3 (k sub-row)
        const int n4 = (tid % 52) * 4;   // 0..204
        const int wbase = m0 - MAXD + n4;
        const bool inb = (wbase >= 0) && (wbase + 3 < WWI);
        #pragma unroll 4
        for (int k0 = 0; k0 < CCH; k0 += 4) {
            const int k = k0 + r;
            float4 v = make_float4(0.f, 0.f, 0.f, 0.f);
            if (inb) v = *(const float4*)(rbase + (size_t)k * PLANE + wbase);
            __half2 h0 = __floats2half2_rn(v.x, v.y);
            __half2 h1 = __floats2half2_rn(v.z, v.w);
            uint2 pk = make_uint2(*(uint32_t*)&h0, *(uint32_t*)&h1);
            *(uint2*)(Bs + k * B_LD + n4) = pk;    // (k*216+n4)%4==0
        }
    }
    __syncthreads();

    // ---------- compute: 8 warps = 4(m) x 2(n); warp tile 32 x (112|96) ----------
    const int wmid = wid & 3;            // m-stripe: tiles 2*wmid, 2*wmid+1
    const int wnid = wid >> 2;           // n-group: 0 -> tiles 0..6, 1 -> 7..12
    const int nt0    = wnid ? 7 : 0;
    const int nCount = wnid ? 6 : 7;

    wmma::fragment<wmma::accumulator, 16, 16, 16, float> acc[2][7];
    #pragma unroll
    for (int i = 0; i < 2; i++)
        #pragma unroll
        for (int j = 0; j < 7; j++)
            wmma::fill_fragment(acc[i][j], 0.0f);

    for (int kt = 0; kt < CCH / 16; kt++) {
        wmma::fragment<wmma::matrix_a, 16, 16, 16, __half, wmma::col_major> af[2];
        const __half* abase = As + kt * 16 * A_LD + wmid * 32;
        wmma::load_matrix_sync(af[0], abase, A_LD);
        wmma::load_matrix_sync(af[1], abase + 16, A_LD);
        #pragma unroll
        for (int j = 0; j < 7; j++) {
            if (j < nCount) {
                wmma::fragment<wmma::matrix_b, 16, 16, 16, __half, wmma::row_major> bf;
                wmma::load_matrix_sync(bf, Bs + kt * 16 * B_LD + (nt0 + j) * 16, B_LD);
                wmma::mma_sync(acc[0][j], af[0], bf, acc[0][j]);
                wmma::mma_sync(acc[1][j], af[1], bf, acc[1][j]);
            }
        }
    }
    __syncthreads();   // all frag reads done before smem reuse

    // ---------- store D tiles to smem [m][208] ----------
    #pragma unroll
    for (int i = 0; i < 2; i++)
        #pragma unroll
        for (int j = 0; j < 7; j++)
            if (j < nCount)
                wmma::store_matrix_sync(Ds + (wmid * 32 + i * 16) * NT + (nt0 + j) * 16,
                                        acc[i][j], NT, wmma::mem_row_major);
    __syncthreads();

    // ---------- band extraction: out[d, m0+m] = Ds[m][m+d] ----------
    const int m  = tid & 127;
    const int ms = (blockIdx.x == 0) ? 0 : 32;   // mask overlap with previous tile
    if (m >= ms) {
        #pragma unroll
        for (int d = tid >> 7; d < DDI; d += 2) {
            out[(((size_t)b * DDI + d) * HH + h) * WWI + m0 + m] = Ds[m * NT + m + d];
        }
    }
}

extern "C" void kernel_launch(void* const* d_in, const int* in_sizes, int n_in,
                              void* d_out, int out_size) {
    const float* left  = (const float*)d_in[0];
    const float* right = (const float*)d_in[1];
    float* out = (float*)d_out;
    (void)in_sizes; (void)n_in; (void)out_size;

    cudaFuncSetAttribute(corr_wmma, cudaFuncAttributeMaxDynamicSharedMemorySize, SMEM_BYTES);
    dim3 grid(4, HH, BB);    // (m-tiles, h, b) = 2048 CTAs
    corr_wmma<<<grid, NTH, SMEM_BYTES>>>(left, right, out);
}

// round 7
// speedup vs baseline: 1.7947x; 1.5691x over previous
#include <cuda_runtime.h>
#include <cuda_fp16.h>
#include <mma.h>
#include <cstdint>

using namespace nvcuda;

#define BB    4
#define CCH   256
#define HH    128
#define WWI   416
#define DDI   81
#define PLANE (HH*WWI)
#define MAXD  40

#define MT    64             // M tile
#define NT    144            // N tile = 64 + 80 band width
#define NTH   256

#define A_LD  72             // [k][m] halves (144 B rows)
#define B_LD  152            // [k][n] halves (304 B rows)
#define A_BYTES (CCH * A_LD * 2)        // 36864
#define B_BYTES (CCH * B_LD * 2)        // 77824
#define SMEM_BYTES (A_BYTES + B_BYTES)  // 114688 -> 2 CTAs/SM

#define D_LD  148            // float stride for D staging (mult of 4, odd word count+1)

__global__ __launch_bounds__(NTH, 2)
void corr_wmma2(const float* __restrict__ left,
                const float* __restrict__ right,
                float* __restrict__ out) {
    extern __shared__ __align__(16) char smem[];
    __half* As = (__half*)smem;                   // [256][72]
    __half* Bs = (__half*)(smem + A_BYTES);       // [256][152]
    float*  Ds = (float*)smem;                    // reused: [64][148]

    const int tid  = threadIdx.x;
    const int wid  = tid >> 5;
    const int tile = blockIdx.x;                  // 0..6
    const int m0   = (tile == 6) ? 352 : tile * MT;
    const int h    = blockIdx.y, b = blockIdx.z;
    const float* lbase = left  + ((size_t)b * CCH * HH + h) * WWI;
    const float* rbase = right + ((size_t)b * CCH * HH + h) * WWI;
    const float S = 1.0f / 256.0f;                // exact, folded into A

    // ---------- fill A: As[k][m] = L[c=k, m0+m] * S ----------
    {
        const int kb = tid >> 4;                  // 0..15
        const int mi = (tid & 15) * 4;            // 0..60
        #pragma unroll 4
        for (int i = 0; i < 16; i++) {
            const int k = kb + 16 * i;
            float4 v = *(const float4*)(lbase + (size_t)k * PLANE + m0 + mi);
            __half2 h0 = __floats2half2_rn(v.x * S, v.y * S);
            __half2 h1 = __floats2half2_rn(v.z * S, v.w * S);
            *(uint2*)(As + k * A_LD + mi) = make_uint2(*(uint32_t*)&h0, *(uint32_t*)&h1);
        }
    }

    // ---------- fill B: Bs[k][n] = R[c=k, m0-40+n], OOB=0 ----------
    {
        #pragma unroll 4
        for (int i = 0; i < 36; i++) {            // 256*36 = 9216 = 256k * 36 float4
            const int idx = tid + i * NTH;
            const int k   = idx / 36;
            const int n4  = (idx - k * 36) * 4;
            const int wb  = m0 - MAXD + n4;
            float4 v = make_float4(0.f, 0.f, 0.f, 0.f);
            if (wb >= 0 && wb + 3 < WWI)
                v = *(const float4*)(rbase + (size_t)k * PLANE + wb);
            __half2 h0 = __floats2half2_rn(v.x, v.y);
            __half2 h1 = __floats2half2_rn(v.z, v.w);
            *(uint2*)(Bs + k * B_LD + n4) = make_uint2(*(uint32_t*)&h0, *(uint32_t*)&h1);
        }
    }
    __syncthreads();

    // ---------- compute: 8 warps = 4(m) x 2(n); warp = 16m x (80|64)n ----------
    const int wmid = wid & 3;                     // m-tile 16*wmid
    const int wnid = wid >> 2;
    const int nt0    = wnid ? 5 : 0;
    const int nCount = wnid ? 4 : 5;

    wmma::fragment<wmma::accumulator, 16, 16, 16, float> acc[5];
    #pragma unroll
    for (int j = 0; j < 5; j++) wmma::fill_fragment(acc[j], 0.0f);

    for (int kt = 0; kt < CCH / 16; kt++) {
        wmma::fragment<wmma::matrix_a, 16, 16, 16, __half, wmma::col_major> af;
        wmma::load_matrix_sync(af, As + kt * 16 * A_LD + wmid * 16, A_LD);
        #pragma unroll
        for (int j = 0; j < 5; j++) {
            if (j < nCount) {
                wmma::fragment<wmma::matrix_b, 16, 16, 16, __half, wmma::row_major> bf;
                wmma::load_matrix_sync(bf, Bs + kt * 16 * B_LD + (nt0 + j) * 16, B_LD);
                wmma::mma_sync(acc[j], af, bf, acc[j]);
            }
        }
    }
    __syncthreads();   // fragment smem reads done before reuse

    // ---------- stage D: Ds[m][n], warp-disjoint regions ----------
    #pragma unroll
    for (int j = 0; j < 5; j++)
        if (j < nCount)
            wmma::store_matrix_sync(Ds + (wmid * 16) * D_LD + (nt0 + j) * 16,
                                    acc[j], D_LD, wmma::mem_row_major);
    __syncthreads();

    // ---------- band extraction: out[d, m0+m] = Ds[m][m+d] ----------
    const int m  = tid & 63;
    const int ms = (tile == 6) ? 32 : 0;          // mask overlap with tile 5
    if (m >= ms) {
        for (int d = tid >> 6; d < DDI; d += 4) {
            out[(((size_t)b * DDI + d) * HH + h) * WWI + m0 + m] = Ds[m * D_LD + m + d];
        }
    }
}

extern "C" void kernel_launch(void* const* d_in, const int* in_sizes, int n_in,
                              void* d_out, int out_size) {
    const float* left  = (const float*)d_in[0];
    const float* right = (const float*)d_in[1];
    float* out = (float*)d_out;
    (void)in_sizes; (void)n_in; (void)out_size;

    cudaFuncSetAttribute(corr_wmma2, cudaFuncAttributeMaxDynamicSharedMemorySize, SMEM_BYTES);
    dim3 grid(7, HH, BB);    // (m-tiles, h, b) = 3584 CTAs
    corr_wmma2<<<grid, NTH, SMEM_BYTES>>>(left, right, out);
}